// round 3
// baseline (speedup 1.0000x reference)
#include <cuda_runtime.h>

typedef unsigned long long ull;

#define C_IN     64
#define INHW     224
#define C_OUT    128
#define OHW      222
#define ICC      8          // input channels per smem chunk
#define TH       8          // output rows per block
#define TW       16         // output cols per block
#define XRROWS   (TH + 2)   // 10 input rows needed
#define XROW     20         // padded smem row width (cols 0..17 valid, 18/19 slop for float4 loads)
#define OC_TILE  64         // output channels per block

// ---- Blackwell packed f32x2 helpers (PTX-only path -> FFMA2 in SASS) ----
__device__ __forceinline__ ull pk(float a, float b) {
    ull r; asm("mov.b64 %0, {%1, %2};" : "=l"(r) : "f"(a), "f"(b)); return r;
}
__device__ __forceinline__ void fma2(ull& d, ull a, ull b) {
    asm("fma.rn.f32x2 %0, %1, %2, %0;" : "+l"(d) : "l"(a), "l"(b));
}
__device__ __forceinline__ float2 unpk(ull v) {
    float2 r; asm("mov.b64 {%0, %1}, %2;" : "=f"(r.x), "=f"(r.y) : "l"(v)); return r;
}

__global__ __launch_bounds__(256, 3)
void conv3x3_f32x2_kernel(const float* __restrict__ x,
                          const float* __restrict__ w,
                          float* __restrict__ out)
{
    // x chunk: ICC ch x 10 rows x 20 cols = 6.25 KB
    __shared__ float  xs[ICC * XRROWS * XROW];
    // weights value-duplicated as (v,v) pairs: [t = ic*9 + kr*3 + ks][oc]  = 36 KB
    __shared__ float2 ws[ICC * 9 * OC_TILE];

    const int tid = threadIdx.x;
    const int ocg = tid >> 4;           // 0..15 -> 4 output channels each
    const int pxg = tid & 15;           // 0..15 pixel groups
    const int pr  = pxg >> 1;           // tile row 0..7
    const int h8  = (pxg & 1) * 8;      // tile col base 0 or 8 (8 px each)

    const int gx0 = blockIdx.x * TW;
    const int gy0 = blockIdx.y * TH;
    const int ocb = blockIdx.z * OC_TILE;

    // 4 oc x 4 pixel-pairs accumulators (64 fp32 in 32 regs)
    ull acc[16];
    #pragma unroll
    for (int i = 0; i < 16; ++i) acc[i] = 0ULL;

    for (int c0 = 0; c0 < C_IN; c0 += ICC) {
        __syncthreads();   // protect previous chunk's smem reads

        // ---- stage x chunk (clamped at image edge; clamped values feed only discarded outputs) ----
        #pragma unroll 1
        for (int i = tid; i < ICC * XRROWS * XROW; i += 256) {
            int ic  = i / (XRROWS * XROW);
            int rem = i - ic * (XRROWS * XROW);
            int r   = rem / XROW;
            int c   = rem - r * XROW;
            int gr = gy0 + r; gr = gr > (INHW - 1) ? (INHW - 1) : gr;
            int gc = gx0 + c; gc = gc > (INHW - 1) ? (INHW - 1) : gc;
            xs[i] = x[((c0 + ic) * INHW + gr) * INHW + gc];
        }
        // ---- stage weights, value-duplicated so FFMA2 B-operand needs no packing ----
        #pragma unroll 1
        for (int i = tid; i < OC_TILE * ICC * 9; i += 256) {
            int oc = i / (ICC * 9);
            int t  = i - oc * (ICC * 9);            // t = ic*9 + kr*3 + ks (contiguous in gmem)
            float v = w[(ocb + oc) * (C_IN * 9) + c0 * 9 + t];
            ws[t * OC_TILE + oc] = make_float2(v, v);
        }
        __syncthreads();

        // ---- compute ----
        #pragma unroll 2
        for (int ic = 0; ic < ICC; ++ic) {
            #pragma unroll
            for (int kr = 0; kr < 3; ++kr) {
                const float4* xr4 =
                    (const float4*)&xs[(ic * XRROWS + pr + kr) * XROW + h8];
                float4 fa = xr4[0];
                float4 fb = xr4[1];
                float4 fc = xr4[2];
                float xf[12];
                xf[0] = fa.x; xf[1] = fa.y; xf[2]  = fa.z; xf[3]  = fa.w;
                xf[4] = fb.x; xf[5] = fb.y; xf[6]  = fb.z; xf[7]  = fb.w;
                xf[8] = fc.x; xf[9] = fc.y; xf[10] = fc.z; xf[11] = fc.w;
                #pragma unroll
                for (int ks = 0; ks < 3; ++ks) {
                    // 4 pixel pairs of the shifted window (adjacent cols -> one f32x2)
                    ull xp0 = pk(xf[ks + 0], xf[ks + 1]);
                    ull xp1 = pk(xf[ks + 2], xf[ks + 3]);
                    ull xp2 = pk(xf[ks + 4], xf[ks + 5]);
                    ull xp3 = pk(xf[ks + 6], xf[ks + 7]);
                    // 4 duplicated weights; broadcast LDS within half-warp
                    const ulonglong2* wp = (const ulonglong2*)
                        &ws[(ic * 9 + kr * 3 + ks) * OC_TILE + ocg * 4];
                    ulonglong2 w01 = wp[0];
                    ulonglong2 w23 = wp[1];
                    fma2(acc[0],  w01.x, xp0); fma2(acc[1],  w01.x, xp1);
                    fma2(acc[2],  w01.x, xp2); fma2(acc[3],  w01.x, xp3);
                    fma2(acc[4],  w01.y, xp0); fma2(acc[5],  w01.y, xp1);
                    fma2(acc[6],  w01.y, xp2); fma2(acc[7],  w01.y, xp3);
                    fma2(acc[8],  w23.x, xp0); fma2(acc[9],  w23.x, xp1);
                    fma2(acc[10], w23.x, xp2); fma2(acc[11], w23.x, xp3);
                    fma2(acc[12], w23.y, xp0); fma2(acc[13], w23.y, xp1);
                    fma2(acc[14], w23.y, xp2); fma2(acc[15], w23.y, xp3);
                }
            }
        }
    }

    // ---- store (every valid output written exactly once; pairs are 8B-aligned) ----
    const int oh = gy0 + pr;
    if (oh < OHW) {
        #pragma unroll
        for (int o = 0; o < 4; ++o) {
            float* orow = out + (size_t)(ocb + ocg * 4 + o) * (OHW * OHW)
                              + oh * OHW + gx0 + h8;
            #pragma unroll
            for (int p = 0; p < 4; ++p) {
                int ow = gx0 + h8 + 2 * p;
                if (ow + 1 < OHW) {
                    *(float2*)(orow + 2 * p) = unpk(acc[o * 4 + p]);
                } else if (ow < OHW) {
                    orow[2 * p] = unpk(acc[o * 4 + p]).x;
                }
            }
        }
    }
}

extern "C" void kernel_launch(void* const* d_in, const int* in_sizes, int n_in,
                              void* d_out, int out_size)
{
    const float* x = (const float*)d_in[0];   // (64, 224, 224) f32
    const float* w = (const float*)d_in[1];   // (128, 64, 3, 3) f32
    float* out = (float*)d_out;               // (128, 222, 222) f32

    dim3 grid((OHW + TW - 1) / TW,            // 14
              (OHW + TH - 1) / TH,            // 28
              C_OUT / OC_TILE);               // 2  -> 784 blocks
    conv3x3_f32x2_kernel<<<grid, 256>>>(x, w, out);
}

// round 4
// speedup vs baseline: 1.2789x; 1.2789x over previous
#include <cuda_runtime.h>

typedef unsigned long long ull;
typedef unsigned int uint;

#define C_IN    64
#define INHW    224
#define INHW2   50176
#define C_OUT   128
#define OHW     222
#define OHW2    49284
#define ICC     8
#define NCHUNK  8          // C_IN / ICC
#define TH      8
#define TW      16
#define XR      10         // input rows per chunk tile
#define XROWF   20         // padded smem row width in floats (80B, 16B-aligned rows)
#define OC_TILE 64

#define WS_BYTES   (ICC*9*OC_TILE*8)          // 36864 (duplicated float2 weights)
#define XE_BYTES   (ICC*XR*XROWF*4)           // 6400
#define XO_BYTES   (ICC*XR*XROWF*4)           // 6400
#define BUF_BYTES  (WS_BYTES+XE_BYTES+XO_BYTES) // 49664
#define SMEM_TOTAL (2*BUF_BYTES)              // 99328 -> occupancy 2

// Pre-duplicated weights: [ocBlk(2)][c0b(8)][icr*9+k (72)][oc(64)] as (v,v) float2.
// Each (ocBlk, c0b) slab is a contiguous 36864B block -> verbatim cp.async.16 staging.
__device__ float2 g_wdup[2 * NCHUNK * ICC * 9 * OC_TILE];

__global__ void prep_wdup_kernel(const float* __restrict__ w) {
    int i = blockIdx.x * 256 + threadIdx.x;
    if (i >= C_OUT * C_IN * 9) return;
    int k  = i % 9;
    int t  = i / 9;
    int ic = t % C_IN;
    int oc = t / C_IN;
    float v = w[i];
    int ocB = oc >> 6, ocr = oc & 63;
    int c0b = ic >> 3, icr = ic & 7;
    g_wdup[((ocB * NCHUNK + c0b) * (ICC * 9) + icr * 9 + k) * OC_TILE + ocr] =
        make_float2(v, v);
}

// ---- Blackwell packed f32x2 FMA (PTX-only path -> FFMA2 in SASS) ----
__device__ __forceinline__ void fma2(ull& d, ull a, ull b) {
    asm("fma.rn.f32x2 %0, %1, %2, %0;" : "+l"(d) : "l"(a), "l"(b));
}
__device__ __forceinline__ float2 unpk(ull v) {
    float2 r; asm("mov.b64 {%0, %1}, %2;" : "=f"(r.x), "=f"(r.y) : "l"(v)); return r;
}

// ---- cp.async helpers ----
__device__ __forceinline__ void cpa16(uint d, const void* s) {
    asm volatile("cp.async.ca.shared.global [%0], [%1], 16;" :: "r"(d), "l"(s) : "memory");
}
__device__ __forceinline__ void cpa4(uint d, const void* s) {
    asm volatile("cp.async.ca.shared.global [%0], [%1], 4;" :: "r"(d), "l"(s) : "memory");
}
__device__ __forceinline__ void cpa_commit() {
    asm volatile("cp.async.commit_group;" ::: "memory");
}
__device__ __forceinline__ void cpa_wait1() {
    asm volatile("cp.async.wait_group 1;" ::: "memory");
}
__device__ __forceinline__ void cpa_wait0() {
    asm volatile("cp.async.wait_group 0;" ::: "memory");
}

// Stage one chunk (weights slab + x even-tile + x odd-shifted-tile) via cp.async.
// Edge handling: row/col indices clamped to 223 — clamped data only ever feeds
// outputs with oh>=222 or ow>=222, which are masked at store.
__device__ __forceinline__ void stage_chunk(
    int c0b, uint buf, const float* __restrict__ x,
    int gx0, int gy0, int ocB, int tid)
{
    // weights: 2304 x 16B, exactly 9 per thread
    const char* slab = (const char*)&g_wdup[(ocB * NCHUNK + c0b) * (ICC * 9) * OC_TILE];
    #pragma unroll
    for (int j = 0; j < 9; ++j) {
        int idx = tid + j * 256;
        cpa16(buf + idx * 16, slab + idx * 16);
    }
    const float* xc = x + c0b * ICC * INHW2;
    // x even tile: cols gx0..gx0+17 -> smem cols 0..17
    uint xeb = buf + WS_BYTES;
    #pragma unroll 1
    for (int idx = tid; idx < ICC * XR * 18; idx += 256) {
        int ic  = idx / (XR * 18);
        int rem = idx - ic * (XR * 18);
        int r   = rem / 18;
        int c   = rem - r * 18;
        int gr  = min(gy0 + r, INHW - 1);
        int gc  = min(gx0 + c, INHW - 1);
        cpa4(xeb + ((ic * XR + r) * XROWF + c) * 4, xc + ic * INHW2 + gr * INHW + gc);
    }
    // x odd tile: cols gx0+1..gx0+16 -> smem cols 0..15
    uint xob = buf + WS_BYTES + XE_BYTES;
    #pragma unroll 1
    for (int idx = tid; idx < ICC * XR * 16; idx += 256) {
        int ic  = idx >> 7;              // /(10*16) ... XR*16=160, not pow2; do exact:
        ic      = idx / (XR * 16);
        int rem = idx - ic * (XR * 16);
        int r   = rem >> 4;
        int c   = rem & 15;
        int gr  = min(gy0 + r, INHW - 1);
        int gc  = min(gx0 + 1 + c, INHW - 1);
        cpa4(xob + ((ic * XR + r) * XROWF + c) * 4, xc + ic * INHW2 + gr * INHW + gc);
    }
}

__global__ __launch_bounds__(256, 2)
void conv3x3_f32x2_db_kernel(const float* __restrict__ x,
                             float* __restrict__ out)
{
    extern __shared__ char smem[];

    const int tid  = threadIdx.x;
    const int ocg2 = tid >> 3;          // 0..31 -> 2 output channels each
    const int pr   = tid & 7;           // output row within tile

    const int gx0 = blockIdx.x * TW;
    const int gy0 = blockIdx.y * TH;
    const int ocB = blockIdx.z;

    // 2 oc x 8 pixel-pairs accumulators
    ull acc[16];
    #pragma unroll
    for (int i = 0; i < 16; ++i) acc[i] = 0ULL;

    uint sbase = (uint)__cvta_generic_to_shared(smem);

    // prologue: stage chunk 0 into buffer 0
    stage_chunk(0, sbase, x, gx0, gy0, ocB, tid);
    cpa_commit();

    for (int c = 0; c < NCHUNK; ++c) {
        if (c + 1 < NCHUNK) {
            stage_chunk(c + 1, sbase + ((c + 1) & 1) * BUF_BYTES, x, gx0, gy0, ocB, tid);
            cpa_commit();
            cpa_wait1();                 // chunk c's group done; c+1 still in flight
        } else {
            cpa_wait0();
        }
        __syncthreads();

        const char* buf = smem + (c & 1) * BUF_BYTES;
        const char* wsb = buf + ocg2 * 16;             // this thread's 2-oc weight pair base
        const char* xeb = buf + WS_BYTES;
        const char* xob = buf + WS_BYTES + XE_BYTES;

        #pragma unroll 2
        for (int ic = 0; ic < ICC; ++ic) {
            #pragma unroll
            for (int kr = 0; kr < 3; ++kr) {
                const int rowoff = ((ic * XR + pr + kr) * XROWF) * 4;
                const ulonglong2* Ep = (const ulonglong2*)(xeb + rowoff);
                const ulonglong2* Op = (const ulonglong2*)(xob + rowoff);
                const ulonglong2* Wp = (const ulonglong2*)(wsb + (ic * 9 + kr * 3) * 512);

                ull e[9];
                {
                    ulonglong2 t0 = Ep[0], t1 = Ep[1], t2 = Ep[2], t3 = Ep[3];
                    e[0] = t0.x; e[1] = t0.y; e[2] = t1.x; e[3] = t1.y;
                    e[4] = t2.x; e[5] = t2.y; e[6] = t3.x; e[7] = t3.y;
                    e[8] = *(const ull*)(xeb + rowoff + 64);
                }
                ull o[8];
                {
                    ulonglong2 t0 = Op[0], t1 = Op[1], t2 = Op[2], t3 = Op[3];
                    o[0] = t0.x; o[1] = t0.y; o[2] = t1.x; o[3] = t1.y;
                    o[4] = t2.x; o[5] = t2.y; o[6] = t3.x; o[7] = t3.y;
                }
                ulonglong2 w0 = Wp[0];    // ks=0, (oc0,oc1) duplicated pairs
                ulonglong2 w1 = Wp[32];   // ks=1 (+512B)
                ulonglong2 w2 = Wp[64];   // ks=2 (+1024B)

                #pragma unroll
                for (int p = 0; p < 8; ++p) {
                    fma2(acc[p],     w0.x, e[p]);
                    fma2(acc[8 + p], w0.y, e[p]);
                }
                #pragma unroll
                for (int p = 0; p < 8; ++p) {
                    fma2(acc[p],     w1.x, o[p]);
                    fma2(acc[8 + p], w1.y, o[p]);
                }
                #pragma unroll
                for (int p = 0; p < 8; ++p) {
                    fma2(acc[p],     w2.x, e[p + 1]);
                    fma2(acc[8 + p], w2.y, e[p + 1]);
                }
            }
        }
        __syncthreads();
    }

    // ---- store: 2 oc x up-to-8 float2 pairs per thread ----
    const int oh = gy0 + pr;
    if (oh < OHW) {
        int npairs = (OHW - gx0) >> 1;     // 8 normally, 7 for the last column block
        if (npairs > 8) npairs = 8;
        #pragma unroll
        for (int o = 0; o < 2; ++o) {
            float2* orow = (float2*)(out + (size_t)(ocB * OC_TILE + ocg2 * 2 + o) * OHW2
                                         + oh * OHW + gx0);
            for (int p = 0; p < npairs; ++p)
                orow[p] = unpk(acc[o * 8 + p]);
        }
    }
}

extern "C" void kernel_launch(void* const* d_in, const int* in_sizes, int n_in,
                              void* d_out, int out_size)
{
    const float* x = (const float*)d_in[0];   // (64, 224, 224) f32
    const float* w = (const float*)d_in[1];   // (128, 64, 3, 3) f32
    float* out = (float*)d_out;               // (128, 222, 222) f32

    // idempotent; executes immediately (not a stream op) so capture-safe
    cudaFuncSetAttribute(conv3x3_f32x2_db_kernel,
                         cudaFuncAttributeMaxDynamicSharedMemorySize, SMEM_TOTAL);

    prep_wdup_kernel<<<(C_OUT * C_IN * 9 + 255) / 256, 256>>>(w);

    dim3 grid((OHW + TW - 1) / TW,            // 14
              (OHW + TH - 1) / TH,            // 28
              C_OUT / OC_TILE);               // 2  -> 784 blocks
    conv3x3_f32x2_db_kernel<<<grid, 256, SMEM_TOTAL>>>(x, out);
}